// round 15
// baseline (speedup 1.0000x reference)
#include <cuda_runtime.h>
#include <cuda_fp16.h>
#include <math.h>

#define BN_ 4
#define CI 256
#define CO 256
#define HN 64
#define WN 64
#define KK 9
#define EPS 1e-5f
#define PAD 40      // offconv smem row pitch (32 data + 8 pad halfs) = 80B
#define PAD2 72     // k_main rows (64 data + 8 pad halfs) = 144B, conflict-free

// ---------------- scratch (device globals; no allocation) ----------------
__device__ __half g_xt[BN_*HN*WN*CI];       // x transposed to [b][y][x][c], fp16
__device__ __half g_woffh[KK*32*CI];        // offset weights fp16 [tap][o(pad32)][c]
__device__ __half g_wth[KK*CO*CI];          // main weights fp16 [tap][o][c]
__device__ int4   g_mbase[BN_*HN*WN*KK];    // 4 corner base indices into g_xt
__device__ float4 g_mw[BN_*HN*WN*KK];       // 4 corner weights (mask*valid premult)

static __device__ __forceinline__ unsigned smem_u32(const void* p) {
    return (unsigned)__cvta_generic_to_shared(p);
}

static __device__ __forceinline__ void mma_f16(float* c, const unsigned* a, const unsigned* b) {
    asm volatile(
        "mma.sync.aligned.m16n8k16.row.col.f32.f16.f16.f32 "
        "{%0,%1,%2,%3}, {%4,%5,%6,%7}, {%8,%9}, {%0,%1,%2,%3};"
        : "+f"(c[0]), "+f"(c[1]), "+f"(c[2]), "+f"(c[3])
        : "r"(a[0]), "r"(a[1]), "r"(a[2]), "r"(a[3]), "r"(b[0]), "r"(b[1]));
}

static __device__ __forceinline__ void ldmat_x4(unsigned* r, unsigned addr) {
    asm volatile("ldmatrix.sync.aligned.m8n8.x4.shared.b16 {%0,%1,%2,%3}, [%4];"
                 : "=r"(r[0]), "=r"(r[1]), "=r"(r[2]), "=r"(r[3]) : "r"(addr));
}

static __device__ __forceinline__ void cp_async16(unsigned dst, const void* src) {
    asm volatile("cp.async.cg.shared.global [%0], [%1], 16;" :: "r"(dst), "l"(src));
}
static __device__ __forceinline__ void cp_async_commit() {
    asm volatile("cp.async.commit_group;");
}
static __device__ __forceinline__ void cp_async_wait0() {
    asm volatile("cp.async.wait_group 0;" ::: "memory");
}

static __device__ __forceinline__ __half2 u2h2(unsigned u) {
    return *reinterpret_cast<const __half2*>(&u);
}
static __device__ __forceinline__ unsigned h22u(__half2 h) {
    return *reinterpret_cast<const unsigned*>(&h);
}

// ---------------- T1: NCHW fp32 -> NHWC fp16 transpose of x ----------------
__global__ void k_transpose_x(const float* __restrict__ x) {
    __shared__ float tile[32][33];
    int b  = blockIdx.z;
    int c0 = blockIdx.y * 32;
    int p0 = blockIdx.x * 32;
    int tx = threadIdx.x, ty = threadIdx.y;
    const float* xb = x + (size_t)b * CI * HN * WN;
    #pragma unroll
    for (int j = 0; j < 32; j += 8)
        tile[ty + j][tx] = xb[(c0 + ty + j) * (HN * WN) + p0 + tx];
    __syncthreads();
    __half* xtb = g_xt + (size_t)b * HN * WN * CI;
    #pragma unroll
    for (int j = 0; j < 32; j += 8)
        xtb[(p0 + ty + j) * CI + c0 + tx] = __float2half_rn(tile[tx][ty + j]);
}

// ---------------- T2: weight re-layouts (fp16) ----------------
__global__ void k_prep_w(const float* __restrict__ w_off, const float* __restrict__ weight) {
    int stride = gridDim.x * blockDim.x;
    int tid = blockIdx.x * blockDim.x + threadIdx.x;
    for (int i = tid; i < KK * 32 * CI; i += stride) {
        int c = i & 255; int to = i >> 8; int o = to & 31; int tap = to >> 5;
        float v = (o < 27) ? w_off[(o * CI + c) * KK + tap] : 0.f;
        g_woffh[i] = __float2half_rn(v);
    }
    for (int i = tid; i < KK * CO * CI; i += stride) {
        int c = i & 255; int to = i >> 8; int o = to & 255; int tap = to >> 8;
        g_wth[i] = __float2half_rn(weight[(o * CI + c) * KK + tap]);
    }
}

// ---------------- O: offset conv, strip-reuse across taps + fused meta ----------------
// dyn smem: strip [3*66][PAD] halfs, bs9 [9*32][PAD] halfs, som [64][32] float
#define OFF_STRIP_ROWS (3 * 66)
#define KOFF_SMEM ((OFF_STRIP_ROWS * PAD + KK * 32 * PAD) * 2 + 64 * 32 * 4)

__global__ __launch_bounds__(256) void k_offconv(const float* __restrict__ b_off) {
    extern __shared__ __align__(16) char odyn[];
    __half* strip = (__half*)odyn;                         // [3*66][PAD]
    __half* bs9   = strip + OFF_STRIP_ROWS * PAD;          // [9*32][PAD]
    float*  som   = (float*)(bs9 + KK * 32 * PAD);         // [64][32]

    int row = blockIdx.x;            // b*64+h
    int b = row >> 6, h = row & 63;
    int tid = threadIdx.x;
    int lane = tid & 31;
    int wid = tid >> 5;
    int wm = wid & 3;                // 16 m-rows each
    int wn = wid >> 2;               // 16 n-cols each

    float acc[2][4];
    #pragma unroll
    for (int i = 0; i < 2; i++)
        #pragma unroll
        for (int j = 0; j < 4; j++) acc[i][j] = 0.f;

    unsigned a_row = (unsigned)(lane & 15);
    unsigned a_koff = (unsigned)((lane >> 4) * 8);
    unsigned strip_base = smem_u32(strip);
    unsigned bs9_base = smem_u32(bs9);
    unsigned b_lane_off;
    {
        int t = lane >> 3, r = lane & 7;
        b_lane_off = (unsigned)(((t >> 1) * 8 + r) * (PAD * 2) + (t & 1) * 16);
    }

    const __half* xb = g_xt + (size_t)(b * HN) * WN * CI;

    for (int c0 = 0; c0 < CI; c0 += 32) {
        __syncthreads();
        // strip load: 3 y-rows x 66 w-positions x 8 quads of 4ch = 1584 tasks
        for (int idx = tid; idx < OFF_STRIP_ROWS * 8; idx += 256) {
            int y_i = idx / (66 * 8);
            int rest = idx - y_i * (66 * 8);
            int wi = rest >> 3;
            int q = rest & 7;
            int y = h + y_i - 1;
            int w = wi - 1;
            uint2 p = make_uint2(0u, 0u);
            if (y >= 0 && y < HN && w >= 0 && w < WN)
                p = *(const uint2*)&xb[((size_t)y * WN + w) * CI + c0 + q * 4];
            *(uint2*)&strip[(y_i * 66 + wi) * PAD + q * 4] = p;
        }
        // B load for all 9 taps: 9 x 32n x 4 parts(8 halfs) = 1152 tasks
        for (int idx = tid; idx < KK * 128; idx += 256) {
            int tap = idx >> 7;
            int r = idx & 127;
            int n = r >> 2, part = r & 3;
            uint4 v = *(const uint4*)&g_woffh[((size_t)(tap * 32 + n)) * CI + c0 + part * 8];
            *(uint4*)&bs9[(tap * 32 + n) * PAD + part * 8] = v;
        }
        __syncthreads();
        #pragma unroll
        for (int tap = 0; tap < KK; tap++) {
            int ky = tap / 3 - 1, kx = tap % 3 - 1;
            unsigned arow0 = (unsigned)((ky + 1) * 66 + kx + 1 + wm * 16);
            #pragma unroll
            for (int ks = 0; ks < 2; ks++) {
                unsigned a[4];
                ldmat_x4(a, strip_base + ((arow0 + a_row) * PAD + ks * 16 + a_koff) * 2);
                unsigned bb4[4];
                ldmat_x4(bb4, bs9_base + (unsigned)((tap * 32 + wn * 16) * (PAD * 2))
                               + (unsigned)(ks * 32) + b_lane_off);
                mma_f16(acc[0], a, bb4);
                mma_f16(acc[1], a, bb4 + 2);
            }
        }
    }
    // stage offset-conv outputs in smem
    __syncthreads();
    {
        int g = lane >> 2;
        int cq = (lane & 3) * 2;
        #pragma unroll
        for (int nf = 0; nf < 2; nf++) {
            #pragma unroll
            for (int half = 0; half < 2; half++) {
                int m = wm * 16 + half * 8 + g;
                #pragma unroll
                for (int j = 0; j < 2; j++) {
                    int n = wn * 16 + nf * 8 + cq + j;
                    som[m * 32 + n] = acc[nf][half * 2 + j];
                }
            }
        }
    }
    __syncthreads();
    // fused meta: 64 m-positions x 9 taps = 576 tasks
    for (int idx = tid; idx < 64 * KK; idx += 256) {
        int k = idx % KK; int w = idx / KK;
        float dy = som[w * 32 + k]      + b_off[k];
        float dx = som[w * 32 + 9 + k]  + b_off[9 + k];
        float mm = som[w * 32 + 18 + k] + b_off[18 + k];
        float mask = 1.f / (1.f + expf(-mm));
        float py = (float)h + (float)(k / 3 - 1) + dy;
        float px = (float)w + (float)(k % 3 - 1) + dx;
        float y0f = floorf(py), x0f = floorf(px);
        float ly = py - y0f, lx = px - x0f;
        int y0 = (int)y0f, x0 = (int)x0f;
        int y1 = y0 + 1, x1 = x0 + 1;
        float vy0 = (y0 >= 0 && y0 < HN) ? 1.f : 0.f;
        float vy1 = (y1 >= 0 && y1 < HN) ? 1.f : 0.f;
        float vx0 = (x0 >= 0 && x0 < WN) ? 1.f : 0.f;
        float vx1 = (x1 >= 0 && x1 < WN) ? 1.f : 0.f;
        int yc0 = min(max(y0, 0), HN - 1), yc1 = min(max(y1, 0), HN - 1);
        int xc0 = min(max(x0, 0), WN - 1), xc1 = min(max(x1, 0), WN - 1);
        float4 wv;
        wv.x = (1.f - ly) * (1.f - lx) * mask * vy0 * vx0;
        wv.y = (1.f - ly) * lx         * mask * vy0 * vx1;
        wv.z = ly * (1.f - lx)         * mask * vy1 * vx0;
        wv.w = ly * lx                 * mask * vy1 * vx1;
        int bb = b * HN * WN;
        int4 bv;
        bv.x = (bb + yc0 * WN + xc0) * CI;
        bv.y = (bb + yc0 * WN + xc1) * CI;
        bv.z = (bb + yc1 * WN + xc0) * CI;
        bv.w = (bb + yc1 * WN + xc1) * CI;
        int gidx = (row * 64 + w) * KK + k;
        g_mbase[gidx] = bv;
        g_mw[gidx] = wv;
    }
}

// ---------------- G: fused sample + fp16 GEMM, BM=128 BN=256 BK=64 ----------------
#define AS_ELEMS (128 * PAD2)
#define BS_ELEMS (256 * PAD2)
#define STEPS 36   // 9 taps * 4 chunks of 64 ch

// half2 bilinear blend of one uint4 (8 ch) from 4 corner uint4s
static __device__ __forceinline__ uint4 blend8(const uint4& r0, const uint4& r1,
                                               const uint4& r2, const uint4& r3,
                                               __half2 w0, __half2 w1, __half2 w2, __half2 w3) {
    uint4 o;
    #pragma unroll
    for (int p = 0; p < 4; p++) {
        __half2 a = __hmul2(w0, u2h2((&r0.x)[p]));
        a = __hfma2(w1, u2h2((&r1.x)[p]), a);
        a = __hfma2(w2, u2h2((&r2.x)[p]), a);
        a = __hfma2(w3, u2h2((&r3.x)[p]), a);
        (&o.x)[p] = h22u(a);
    }
    return o;
}

__global__ __launch_bounds__(512, 1) void k_main(const float* __restrict__ bias,
                                              const float* __restrict__ gamma,
                                              const float* __restrict__ beta,
                                              const float* __restrict__ rmean,
                                              const float* __restrict__ rvar,
                                              float* __restrict__ out) {
    extern __shared__ __align__(16) char dyn[];
    __half* As    = (__half*)dyn;                         // [2][AS_ELEMS]
    __half* Bs    = As + 2 * AS_ELEMS;                    // [2][BS_ELEMS]
    int4*   SB    = (int4*)(Bs + 2 * BS_ELEMS);           // [2][128]
    float4* SW    = (float4*)(SB + 2 * 128);              // [2][128]
    float*  s_scale = (float*)(SW + 2 * 128);             // [256]
    float*  s_shift = s_scale + 256;                      // [256]

    int m_base = blockIdx.x * 128;
    int tid = threadIdx.x;
    int lane = tid & 31;
    int wid = tid >> 5;
    int wm = wid & 3;          // m-warp: 32 rows
    int wn = wid >> 2;         // n-warp 0..3: 64 cols

    if (tid < 256) {
        float inv = gamma[tid] * rsqrtf(rvar[tid] + EPS);
        s_scale[tid] = inv;
        s_shift[tid] = beta[tid] - rmean[tid] * inv + bias[tid] * inv;
    }
    if (tid < 128)      SB[tid] = g_mbase[(m_base + tid) * KK + 0];
    else if (tid < 256) SW[tid - 128] = g_mw[(m_base + tid - 128) * KK + 0];
    __syncthreads();

    float acc[2][8][4];
    #pragma unroll
    for (int i = 0; i < 2; i++)
        #pragma unroll
        for (int j = 0; j < 8; j++)
            #pragma unroll
            for (int q = 0; q < 4; q++) acc[i][j][q] = 0.f;

    unsigned a_row = (unsigned)(lane & 15);
    unsigned a_koff = (unsigned)((lane >> 4) * 8);
    unsigned as_base = smem_u32(As);
    unsigned bs_base = smem_u32(Bs);
    unsigned b_lane_off;
    {
        int t = lane >> 3, r = lane & 7;
        b_lane_off = (unsigned)(((t >> 1) * 8 + r) * (PAD2 * 2) + (t & 1) * 16);
    }

    // gather: 1024 tasks/step (128 m x 8 octs of 8 ch); 2 per thread.
    const int tk_m[2]   = { tid >> 3, (tid + 512) >> 3 };
    const int tk_oct[2] = { tid & 7,  tid & 7 };
    const int as_off[2] = { tk_m[0] * PAD2 + tk_oct[0] * 8,
                            tk_m[1] * PAD2 + tk_oct[1] * 8 };

    // ---- build step 0 into buffer 0 (blocking) ----
    {
        #pragma unroll
        for (int t = 0; t < 2; t++) {
            int4 bs = SB[tk_m[t]];
            float4 wf = SW[tk_m[t]];
            int c = tk_oct[t] * 8;
            uint4 r0 = *(const uint4*)&g_xt[bs.x + c];
            uint4 r1 = *(const uint4*)&g_xt[bs.y + c];
            uint4 r2 = *(const uint4*)&g_xt[bs.z + c];
            uint4 r3 = *(const uint4*)&g_xt[bs.w + c];
            __half2 w0 = __float2half2_rn(wf.x), w1 = __float2half2_rn(wf.y);
            __half2 w2 = __float2half2_rn(wf.z), w3 = __float2half2_rn(wf.w);
            *(uint4*)&As[as_off[t]] = blend8(r0, r1, r2, r3, w0, w1, w2, w3);
        }
        #pragma unroll
        for (int j = 0; j < 4; j++) {
            int idx = tid + 512 * j;          // 0..2047
            int n = idx >> 3;
            int part = idx & 7;
            uint4 v = *(const uint4*)&g_wth[(size_t)n * CI + part * 8];
            *(uint4*)&Bs[n * PAD2 + part * 8] = v;
        }
    }
    __syncthreads();

    for (int s = 0; s < STEPS; s++) {
        int cur = s & 1, nxt = cur ^ 1;
        int tap = s >> 2;

        // prefetch next tap's metadata (parity-buffered)
        if ((s & 3) == 0 && tap + 1 < KK) {
            int p = (tap + 1) & 1;
            if (tid < 128)      SB[p * 128 + tid] = g_mbase[(m_base + tid) * KK + tap + 1];
            else if (tid < 256) SW[p * 128 + tid - 128] = g_mw[(m_base + tid - 128) * KK + tap + 1];
        }

        bool have_next = (s + 1 < STEPS);
        int tap1 = (s + 1) >> 2;
        int c01 = ((s + 1) & 3) * 64;
        const int4*   SBt = SB + (tap1 & 1) * 128;
        const float4* SWt = SW + (tap1 & 1) * 128;
        unsigned ab = as_base + cur * (AS_ELEMS * 2);
        unsigned bb_base = bs_base + cur * (BS_ELEMS * 2) + (unsigned)(wn * 64) * (PAD2 * 2) + b_lane_off;

        // ---- cp.async B(s+1) (reg-free, earliest issue) ----
        if (have_next) {
            const __half* wb = g_wth + (size_t)tap1 * CO * CI + c01;
            unsigned bdst = bs_base + (unsigned)(nxt * BS_ELEMS * 2);
            #pragma unroll
            for (int j = 0; j < 4; j++) {
                int idx = tid + 512 * j;
                int n = idx >> 3;
                int part = idx & 7;
                cp_async16(bdst + (unsigned)(n * PAD2 + part * 8) * 2, &wb[(size_t)n * CI + part * 8]);
            }
            cp_async_commit();
        }

        // ---- gather task0 LDGs ----
        uint4 r0, r1, r2, r3;
        float4 wf;
        if (have_next) {
            int4 bs = SBt[tk_m[0]];
            wf = SWt[tk_m[0]];
            int c = c01 + tk_oct[0] * 8;
            r0 = *(const uint4*)&g_xt[bs.x + c];
            r1 = *(const uint4*)&g_xt[bs.y + c];
            r2 = *(const uint4*)&g_xt[bs.z + c];
            r3 = *(const uint4*)&g_xt[bs.w + c];
        }

        // ---- mma ks 0,1 ----
        #pragma unroll
        for (int ks = 0; ks < 2; ks++) {
            unsigned a[2][4];
            #pragma unroll
            for (int mf = 0; mf < 2; mf++) {
                unsigned row = (unsigned)(wm * 32 + mf * 16) + a_row;
                ldmat_x4(a[mf], ab + row * (PAD2 * 2) + (ks * 16 + a_koff) * 2);
            }
            #pragma unroll
            for (int nf2 = 0; nf2 < 4; nf2++) {
                unsigned bb4[4];
                ldmat_x4(bb4, bb_base + (unsigned)(nf2 * 16) * (PAD2 * 2) + (unsigned)(ks * 32));
                #pragma unroll
                for (int mf = 0; mf < 2; mf++) {
                    mma_f16(acc[mf][nf2 * 2],     a[mf], bb4);
                    mma_f16(acc[mf][nf2 * 2 + 1], a[mf], bb4 + 2);
                }
            }
        }

        // ---- blend+STS task0; gather task1 LDGs ----
        if (have_next) {
            __half2 w0 = __float2half2_rn(wf.x), w1 = __float2half2_rn(wf.y);
            __half2 w2 = __float2half2_rn(wf.z), w3 = __float2half2_rn(wf.w);
            *(uint4*)&As[nxt * AS_ELEMS + as_off[0]] = blend8(r0, r1, r2, r3, w0, w1, w2, w3);
            int4 bs = SBt[tk_m[1]];
            wf = SWt[tk_m[1]];
            int c = c01 + tk_oct[1] * 8;
            r0 = *(const uint4*)&g_xt[bs.x + c];
            r1 = *(const uint4*)&g_xt[bs.y + c];
            r2 = *(const uint4*)&g_xt[bs.z + c];
            r3 = *(const uint4*)&g_xt[bs.w + c];
        }

        // ---- mma ks 2,3 ----
        #pragma unroll
        for (int ks = 2; ks < 4; ks++) {
            unsigned a[2][4];
            #pragma unroll
            for (int mf = 0; mf < 2; mf++) {
                unsigned row = (unsigned)(wm * 32 + mf * 16) + a_row;
                ldmat_x4(a[mf], ab + row * (PAD2 * 2) + (ks * 16 + a_koff) * 2);
            }
            #pragma unroll
            for (int nf2 = 0; nf2 < 4; nf2++) {
                unsigned bb4[4];
                ldmat_x4(bb4, bb_base + (unsigned)(nf2 * 16) * (PAD2 * 2) + (unsigned)(ks * 32));
                #pragma unroll
                for (int mf = 0; mf < 2; mf++) {
                    mma_f16(acc[mf][nf2 * 2],     a[mf], bb4);
                    mma_f16(acc[mf][nf2 * 2 + 1], a[mf], bb4 + 2);
                }
            }
        }

        // ---- blend+STS task1; drain cp.async ----
        if (have_next) {
            __half2 w0 = __float2half2_rn(wf.x), w1 = __float2half2_rn(wf.y);
            __half2 w2 = __float2half2_rn(wf.z), w3 = __float2half2_rn(wf.w);
            *(uint4*)&As[nxt * AS_ELEMS + as_off[1]] = blend8(r0, r1, r2, r3, w0, w1, w2, w3);
            cp_async_wait0();
        }
        __syncthreads();
    }

    // ---- epilogue: BN(+bias) + ReLU, write NCHW ----
    int g = lane >> 2;
    int cq = (lane & 3) * 2;
    #pragma unroll
    for (int mf = 0; mf < 2; mf++) {
        int row0 = m_base + wm * 32 + mf * 16 + g;
        #pragma unroll
        for (int half = 0; half < 2; half++) {
            int m = row0 + half * 8;
            int b = m >> 12, h = (m >> 6) & 63, w = m & 63;
            float* orow = out + ((size_t)b * CO * HN + h) * WN + w;
            #pragma unroll
            for (int nf = 0; nf < 8; nf++) {
                int nl0 = wn * 64 + nf * 8 + cq;
                #pragma unroll
                for (int j = 0; j < 2; j++) {
                    int nl = nl0 + j;
                    float v = acc[mf][nf][half * 2 + j] * s_scale[nl] + s_shift[nl];
                    orow[(size_t)nl * HN * WN] = fmaxf(v, 0.f);
                }
            }
        }
    }
}

// ---------------- launch ----------------
#define KMAIN_SMEM (2*AS_ELEMS*2 + 2*BS_ELEMS*2 + 2*128*16 + 2*128*16 + 2*256*4)

extern "C" void kernel_launch(void* const* d_in, const int* in_sizes, int n_in,
                              void* d_out, int out_size) {
    const float* x      = (const float*)d_in[0];
    const float* w_off  = (const float*)d_in[1];
    const float* b_off  = (const float*)d_in[2];
    const float* weight = (const float*)d_in[3];
    const float* bias   = (const float*)d_in[4];
    const float* gamma  = (const float*)d_in[5];
    const float* beta   = (const float*)d_in[6];
    const float* rmean  = (const float*)d_in[7];
    const float* rvar   = (const float*)d_in[8];
    float* out = (float*)d_out;

    static bool attr_done = false;
    if (!attr_done) {
        cudaFuncSetAttribute(k_main, cudaFuncAttributeMaxDynamicSharedMemorySize, KMAIN_SMEM);
        cudaFuncSetAttribute(k_offconv, cudaFuncAttributeMaxDynamicSharedMemorySize, KOFF_SMEM);
        attr_done = true;
    }

    dim3 tgrid(HN * WN / 32, CI / 32, BN_);
    k_transpose_x<<<tgrid, dim3(32, 8)>>>(x);
    k_prep_w<<<256, 256>>>(w_off, weight);
    k_offconv<<<BN_ * HN, 256, KOFF_SMEM>>>(b_off);
    k_main<<<BN_ * HN * WN / 128, 512, KMAIN_SMEM>>>(bias, gamma, beta, rmean, rvar, out);
}

// round 16
// speedup vs baseline: 1.0174x; 1.0174x over previous
#include <cuda_runtime.h>
#include <cuda_fp16.h>
#include <math.h>

#define BN_ 4
#define CI 256
#define CO 256
#define HN 64
#define WN 64
#define KK 9
#define EPS 1e-5f
#define PAD 40      // offconv smem row pitch (32 data + 8 pad halfs) = 80B
#define PAD2 72     // k_main rows (64 data + 8 pad halfs) = 144B, conflict-free

// ---------------- scratch (device globals; no allocation) ----------------
__device__ __half g_xt[BN_*HN*WN*CI];       // x transposed to [b][y][x][c], fp16
__device__ __half g_woffh[KK*32*CI];        // offset weights fp16 [tap][o(pad32)][c]
__device__ __half g_wth[KK*CO*CI];          // main weights fp16 [tap][o][c]
__device__ int4   g_mbase[BN_*HN*WN*KK];    // 4 corner base indices into g_xt
__device__ float4 g_mw[BN_*HN*WN*KK];       // 4 corner weights (mask*valid premult)

static __device__ __forceinline__ unsigned smem_u32(const void* p) {
    return (unsigned)__cvta_generic_to_shared(p);
}

static __device__ __forceinline__ void mma_f16(float* c, const unsigned* a, const unsigned* b) {
    asm volatile(
        "mma.sync.aligned.m16n8k16.row.col.f32.f16.f16.f32 "
        "{%0,%1,%2,%3}, {%4,%5,%6,%7}, {%8,%9}, {%0,%1,%2,%3};"
        : "+f"(c[0]), "+f"(c[1]), "+f"(c[2]), "+f"(c[3])
        : "r"(a[0]), "r"(a[1]), "r"(a[2]), "r"(a[3]), "r"(b[0]), "r"(b[1]));
}

static __device__ __forceinline__ void ldmat_x4(unsigned* r, unsigned addr) {
    asm volatile("ldmatrix.sync.aligned.m8n8.x4.shared.b16 {%0,%1,%2,%3}, [%4];"
                 : "=r"(r[0]), "=r"(r[1]), "=r"(r[2]), "=r"(r[3]) : "r"(addr));
}

static __device__ __forceinline__ void cp_async16(unsigned dst, const void* src) {
    asm volatile("cp.async.cg.shared.global [%0], [%1], 16;" :: "r"(dst), "l"(src));
}
static __device__ __forceinline__ void cp_async_commit() {
    asm volatile("cp.async.commit_group;");
}
static __device__ __forceinline__ void cp_async_wait0() {
    asm volatile("cp.async.wait_group 0;" ::: "memory");
}

static __device__ __forceinline__ __half2 u2h2(unsigned u) {
    return *reinterpret_cast<const __half2*>(&u);
}
static __device__ __forceinline__ unsigned h22u(__half2 h) {
    return *reinterpret_cast<const unsigned*>(&h);
}

// ---------------- P: fused transpose + weight re-layout ----------------
// blocks [0, 4096): NCHW fp32 -> NHWC fp16 transpose of x (32x32 tiles)
// blocks [4096, 4352): per-o coalesced relayout of main weights
// blocks [4352, 4384): offset weights (o<27 real, o>=27 zero-pad)
#define PREP_TRANSPOSE_BLKS (BN_ * (CI / 32) * (HN * WN / 32))   // 4096

__global__ __launch_bounds__(256) void k_prep(const float* __restrict__ x,
                                              const float* __restrict__ w_off,
                                              const float* __restrict__ weight) {
    int bid = blockIdx.x;
    int tid = threadIdx.x;
    if (bid < PREP_TRANSPOSE_BLKS) {
        __shared__ float tile[32][33];
        int b  = bid >> 10;
        int c0 = ((bid >> 7) & 7) * 32;
        int p0 = (bid & 127) * 32;
        int tx = tid & 31, ty = tid >> 5;
        const float* xb = x + (size_t)b * CI * HN * WN;
        #pragma unroll
        for (int j = 0; j < 32; j += 8)
            tile[ty + j][tx] = xb[(c0 + ty + j) * (HN * WN) + p0 + tx];
        __syncthreads();
        __half* xtb = g_xt + (size_t)b * HN * WN * CI;
        #pragma unroll
        for (int j = 0; j < 32; j += 8)
            xtb[(p0 + ty + j) * CI + c0 + tx] = __float2half_rn(tile[tx][ty + j]);
    } else if (bid < PREP_TRANSPOSE_BLKS + CO) {
        // main weight: one block per o; coalesced read of weight[o][*][*]
        __shared__ float wrow[CI * KK];
        int o = bid - PREP_TRANSPOSE_BLKS;
        const float* src = weight + (size_t)o * CI * KK;
        #pragma unroll
        for (int j = 0; j < KK; j++)
            wrow[tid + 256 * j] = src[tid + 256 * j];
        __syncthreads();
        int c = tid;
        #pragma unroll
        for (int tap = 0; tap < KK; tap++)
            g_wth[((size_t)tap * CO + o) * CI + c] = __float2half_rn(wrow[c * KK + tap]);
    } else {
        // offset weight: one block per padded o (32 total)
        __shared__ float wrow[CI * KK];
        int o = bid - PREP_TRANSPOSE_BLKS - CO;
        if (o < 27) {
            const float* src = w_off + (size_t)o * CI * KK;
            #pragma unroll
            for (int j = 0; j < KK; j++)
                wrow[tid + 256 * j] = src[tid + 256 * j];
        } else {
            #pragma unroll
            for (int j = 0; j < KK; j++)
                wrow[tid + 256 * j] = 0.f;
        }
        __syncthreads();
        int c = tid;
        #pragma unroll
        for (int tap = 0; tap < KK; tap++)
            g_woffh[((size_t)tap * 32 + o) * CI + c] = __float2half_rn(wrow[c * KK + tap]);
    }
}

// ---------------- O: offset conv, strip-reuse across taps + fused meta ----------------
#define OFF_STRIP_ROWS (3 * 66)
#define KOFF_SMEM ((OFF_STRIP_ROWS * PAD + KK * 32 * PAD) * 2 + 64 * 32 * 4)

__global__ __launch_bounds__(256) void k_offconv(const float* __restrict__ b_off) {
    extern __shared__ __align__(16) char odyn[];
    __half* strip = (__half*)odyn;                         // [3*66][PAD]
    __half* bs9   = strip + OFF_STRIP_ROWS * PAD;          // [9*32][PAD]
    float*  som   = (float*)(bs9 + KK * 32 * PAD);         // [64][32]

    int row = blockIdx.x;            // b*64+h
    int b = row >> 6, h = row & 63;
    int tid = threadIdx.x;
    int lane = tid & 31;
    int wid = tid >> 5;
    int wm = wid & 3;                // 16 m-rows each
    int wn = wid >> 2;               // 16 n-cols each

    float acc[2][4];
    #pragma unroll
    for (int i = 0; i < 2; i++)
        #pragma unroll
        for (int j = 0; j < 4; j++) acc[i][j] = 0.f;

    unsigned a_row = (unsigned)(lane & 15);
    unsigned a_koff = (unsigned)((lane >> 4) * 8);
    unsigned strip_base = smem_u32(strip);
    unsigned bs9_base = smem_u32(bs9);
    unsigned b_lane_off;
    {
        int t = lane >> 3, r = lane & 7;
        b_lane_off = (unsigned)(((t >> 1) * 8 + r) * (PAD * 2) + (t & 1) * 16);
    }

    const __half* xb = g_xt + (size_t)(b * HN) * WN * CI;

    for (int c0 = 0; c0 < CI; c0 += 32) {
        __syncthreads();
        for (int idx = tid; idx < OFF_STRIP_ROWS * 8; idx += 256) {
            int y_i = idx / (66 * 8);
            int rest = idx - y_i * (66 * 8);
            int wi = rest >> 3;
            int q = rest & 7;
            int y = h + y_i - 1;
            int w = wi - 1;
            uint2 p = make_uint2(0u, 0u);
            if (y >= 0 && y < HN && w >= 0 && w < WN)
                p = *(const uint2*)&xb[((size_t)y * WN + w) * CI + c0 + q * 4];
            *(uint2*)&strip[(y_i * 66 + wi) * PAD + q * 4] = p;
        }
        for (int idx = tid; idx < KK * 128; idx += 256) {
            int tap = idx >> 7;
            int r = idx & 127;
            int n = r >> 2, part = r & 3;
            uint4 v = *(const uint4*)&g_woffh[((size_t)(tap * 32 + n)) * CI + c0 + part * 8];
            *(uint4*)&bs9[(tap * 32 + n) * PAD + part * 8] = v;
        }
        __syncthreads();
        #pragma unroll
        for (int tap = 0; tap < KK; tap++) {
            int ky = tap / 3 - 1, kx = tap % 3 - 1;
            unsigned arow0 = (unsigned)((ky + 1) * 66 + kx + 1 + wm * 16);
            #pragma unroll
            for (int ks = 0; ks < 2; ks++) {
                unsigned a[4];
                ldmat_x4(a, strip_base + ((arow0 + a_row) * PAD + ks * 16 + a_koff) * 2);
                unsigned bb4[4];
                ldmat_x4(bb4, bs9_base + (unsigned)((tap * 32 + wn * 16) * (PAD * 2))
                               + (unsigned)(ks * 32) + b_lane_off);
                mma_f16(acc[0], a, bb4);
                mma_f16(acc[1], a, bb4 + 2);
            }
        }
    }
    __syncthreads();
    {
        int g = lane >> 2;
        int cq = (lane & 3) * 2;
        #pragma unroll
        for (int nf = 0; nf < 2; nf++) {
            #pragma unroll
            for (int half = 0; half < 2; half++) {
                int m = wm * 16 + half * 8 + g;
                #pragma unroll
                for (int j = 0; j < 2; j++) {
                    int n = wn * 16 + nf * 8 + cq + j;
                    som[m * 32 + n] = acc[nf][half * 2 + j];
                }
            }
        }
    }
    __syncthreads();
    for (int idx = tid; idx < 64 * KK; idx += 256) {
        int k = idx % KK; int w = idx / KK;
        float dy = som[w * 32 + k]      + b_off[k];
        float dx = som[w * 32 + 9 + k]  + b_off[9 + k];
        float mm = som[w * 32 + 18 + k] + b_off[18 + k];
        float mask = 1.f / (1.f + expf(-mm));
        float py = (float)h + (float)(k / 3 - 1) + dy;
        float px = (float)w + (float)(k % 3 - 1) + dx;
        float y0f = floorf(py), x0f = floorf(px);
        float ly = py - y0f, lx = px - x0f;
        int y0 = (int)y0f, x0 = (int)x0f;
        int y1 = y0 + 1, x1 = x0 + 1;
        float vy0 = (y0 >= 0 && y0 < HN) ? 1.f : 0.f;
        float vy1 = (y1 >= 0 && y1 < HN) ? 1.f : 0.f;
        float vx0 = (x0 >= 0 && x0 < WN) ? 1.f : 0.f;
        float vx1 = (x1 >= 0 && x1 < WN) ? 1.f : 0.f;
        int yc0 = min(max(y0, 0), HN - 1), yc1 = min(max(y1, 0), HN - 1);
        int xc0 = min(max(x0, 0), WN - 1), xc1 = min(max(x1, 0), WN - 1);
        float4 wv;
        wv.x = (1.f - ly) * (1.f - lx) * mask * vy0 * vx0;
        wv.y = (1.f - ly) * lx         * mask * vy0 * vx1;
        wv.z = ly * (1.f - lx)         * mask * vy1 * vx0;
        wv.w = ly * lx                 * mask * vy1 * vx1;
        int bb = b * HN * WN;
        int4 bv;
        bv.x = (bb + yc0 * WN + xc0) * CI;
        bv.y = (bb + yc0 * WN + xc1) * CI;
        bv.z = (bb + yc1 * WN + xc0) * CI;
        bv.w = (bb + yc1 * WN + xc1) * CI;
        int gidx = (row * 64 + w) * KK + k;
        g_mbase[gidx] = bv;
        g_mw[gidx] = wv;
    }
}

// ---------------- G: fused sample + fp16 GEMM, BM=128 BN=256 BK=64 ----------------
#define AS_ELEMS (128 * PAD2)
#define BS_ELEMS (256 * PAD2)
#define STEPS 36   // 9 taps * 4 chunks of 64 ch

static __device__ __forceinline__ uint4 blend8(const uint4& r0, const uint4& r1,
                                               const uint4& r2, const uint4& r3,
                                               __half2 w0, __half2 w1, __half2 w2, __half2 w3) {
    uint4 o;
    #pragma unroll
    for (int p = 0; p < 4; p++) {
        __half2 a = __hmul2(w0, u2h2((&r0.x)[p]));
        a = __hfma2(w1, u2h2((&r1.x)[p]), a);
        a = __hfma2(w2, u2h2((&r2.x)[p]), a);
        a = __hfma2(w3, u2h2((&r3.x)[p]), a);
        (&o.x)[p] = h22u(a);
    }
    return o;
}

__global__ __launch_bounds__(512, 1) void k_main(const float* __restrict__ bias,
                                              const float* __restrict__ gamma,
                                              const float* __restrict__ beta,
                                              const float* __restrict__ rmean,
                                              const float* __restrict__ rvar,
                                              float* __restrict__ out) {
    extern __shared__ __align__(16) char dyn[];
    __half* As    = (__half*)dyn;                         // [2][AS_ELEMS]
    __half* Bs    = As + 2 * AS_ELEMS;                    // [2][BS_ELEMS]
    int4*   SB    = (int4*)(Bs + 2 * BS_ELEMS);           // [2][128]
    float4* SW    = (float4*)(SB + 2 * 128);              // [2][128]
    float*  s_scale = (float*)(SW + 2 * 128);             // [256]
    float*  s_shift = s_scale + 256;                      // [256]

    int m_base = blockIdx.x * 128;
    int tid = threadIdx.x;
    int lane = tid & 31;
    int wid = tid >> 5;
    int wm = wid & 3;          // m-warp: 32 rows
    int wn = wid >> 2;         // n-warp 0..3: 64 cols

    if (tid < 256) {
        float inv = gamma[tid] * rsqrtf(rvar[tid] + EPS);
        s_scale[tid] = inv;
        s_shift[tid] = beta[tid] - rmean[tid] * inv + bias[tid] * inv;
    }
    if (tid < 128)      SB[tid] = g_mbase[(m_base + tid) * KK + 0];
    else if (tid < 256) SW[tid - 128] = g_mw[(m_base + tid - 128) * KK + 0];
    __syncthreads();

    float acc[2][8][4];
    #pragma unroll
    for (int i = 0; i < 2; i++)
        #pragma unroll
        for (int j = 0; j < 8; j++)
            #pragma unroll
            for (int q = 0; q < 4; q++) acc[i][j][q] = 0.f;

    unsigned a_row = (unsigned)(lane & 15);
    unsigned a_koff = (unsigned)((lane >> 4) * 8);
    unsigned as_base = smem_u32(As);
    unsigned bs_base = smem_u32(Bs);
    unsigned b_lane_off;
    {
        int t = lane >> 3, r = lane & 7;
        b_lane_off = (unsigned)(((t >> 1) * 8 + r) * (PAD2 * 2) + (t & 1) * 16);
    }

    const int tk_m[2]   = { tid >> 3, (tid + 512) >> 3 };
    const int tk_oct[2] = { tid & 7,  tid & 7 };
    const int as_off[2] = { tk_m[0] * PAD2 + tk_oct[0] * 8,
                            tk_m[1] * PAD2 + tk_oct[1] * 8 };

    // ---- build step 0 into buffer 0 (blocking) ----
    {
        #pragma unroll
        for (int t = 0; t < 2; t++) {
            int4 bs = SB[tk_m[t]];
            float4 wf = SW[tk_m[t]];
            int c = tk_oct[t] * 8;
            uint4 r0 = *(const uint4*)&g_xt[bs.x + c];
            uint4 r1 = *(const uint4*)&g_xt[bs.y + c];
            uint4 r2 = *(const uint4*)&g_xt[bs.z + c];
            uint4 r3 = *(const uint4*)&g_xt[bs.w + c];
            __half2 w0 = __float2half2_rn(wf.x), w1 = __float2half2_rn(wf.y);
            __half2 w2 = __float2half2_rn(wf.z), w3 = __float2half2_rn(wf.w);
            *(uint4*)&As[as_off[t]] = blend8(r0, r1, r2, r3, w0, w1, w2, w3);
        }
        #pragma unroll
        for (int j = 0; j < 4; j++) {
            int idx = tid + 512 * j;          // 0..2047
            int n = idx >> 3;
            int part = idx & 7;
            uint4 v = *(const uint4*)&g_wth[(size_t)n * CI + part * 8];
            *(uint4*)&Bs[n * PAD2 + part * 8] = v;
        }
    }
    __syncthreads();

    for (int s = 0; s < STEPS; s++) {
        int cur = s & 1, nxt = cur ^ 1;
        int tap = s >> 2;

        if ((s & 3) == 0 && tap + 1 < KK) {
            int p = (tap + 1) & 1;
            if (tid < 128)      SB[p * 128 + tid] = g_mbase[(m_base + tid) * KK + tap + 1];
            else if (tid < 256) SW[p * 128 + tid - 128] = g_mw[(m_base + tid - 128) * KK + tap + 1];
        }

        bool have_next = (s + 1 < STEPS);
        int tap1 = (s + 1) >> 2;
        int c01 = ((s + 1) & 3) * 64;
        const int4*   SBt = SB + (tap1 & 1) * 128;
        const float4* SWt = SW + (tap1 & 1) * 128;
        unsigned ab = as_base + cur * (AS_ELEMS * 2);
        unsigned bb_base = bs_base + cur * (BS_ELEMS * 2) + (unsigned)(wn * 64) * (PAD2 * 2) + b_lane_off;

        if (have_next) {
            const __half* wb = g_wth + (size_t)tap1 * CO * CI + c01;
            unsigned bdst = bs_base + (unsigned)(nxt * BS_ELEMS * 2);
            #pragma unroll
            for (int j = 0; j < 4; j++) {
                int idx = tid + 512 * j;
                int n = idx >> 3;
                int part = idx & 7;
                cp_async16(bdst + (unsigned)(n * PAD2 + part * 8) * 2, &wb[(size_t)n * CI + part * 8]);
            }
            cp_async_commit();
        }

        uint4 r0, r1, r2, r3;
        float4 wf;
        if (have_next) {
            int4 bs = SBt[tk_m[0]];
            wf = SWt[tk_m[0]];
            int c = c01 + tk_oct[0] * 8;
            r0 = *(const uint4*)&g_xt[bs.x + c];
            r1 = *(const uint4*)&g_xt[bs.y + c];
            r2 = *(const uint4*)&g_xt[bs.z + c];
            r3 = *(const uint4*)&g_xt[bs.w + c];
        }

        #pragma unroll
        for (int ks = 0; ks < 2; ks++) {
            unsigned a[2][4];
            #pragma unroll
            for (int mf = 0; mf < 2; mf++) {
                unsigned row = (unsigned)(wm * 32 + mf * 16) + a_row;
                ldmat_x4(a[mf], ab + row * (PAD2 * 2) + (ks * 16 + a_koff) * 2);
            }
            #pragma unroll
            for (int nf2 = 0; nf2 < 4; nf2++) {
                unsigned bb4[4];
                ldmat_x4(bb4, bb_base + (unsigned)(nf2 * 16) * (PAD2 * 2) + (unsigned)(ks * 32));
                #pragma unroll
                for (int mf = 0; mf < 2; mf++) {
                    mma_f16(acc[mf][nf2 * 2],     a[mf], bb4);
                    mma_f16(acc[mf][nf2 * 2 + 1], a[mf], bb4 + 2);
                }
            }
        }

        if (have_next) {
            __half2 w0 = __float2half2_rn(wf.x), w1 = __float2half2_rn(wf.y);
            __half2 w2 = __float2half2_rn(wf.z), w3 = __float2half2_rn(wf.w);
            *(uint4*)&As[nxt * AS_ELEMS + as_off[0]] = blend8(r0, r1, r2, r3, w0, w1, w2, w3);
            int4 bs = SBt[tk_m[1]];
            wf = SWt[tk_m[1]];
            int c = c01 + tk_oct[1] * 8;
            r0 = *(const uint4*)&g_xt[bs.x + c];
            r1 = *(const uint4*)&g_xt[bs.y + c];
            r2 = *(const uint4*)&g_xt[bs.z + c];
            r3 = *(const uint4*)&g_xt[bs.w + c];
        }

        #pragma unroll
        for (int ks = 2; ks < 4; ks++) {
            unsigned a[2][4];
            #pragma unroll
            for (int mf = 0; mf < 2; mf++) {
                unsigned row = (unsigned)(wm * 32 + mf * 16) + a_row;
                ldmat_x4(a[mf], ab + row * (PAD2 * 2) + (ks * 16 + a_koff) * 2);
            }
            #pragma unroll
            for (int nf2 = 0; nf2 < 4; nf2++) {
                unsigned bb4[4];
                ldmat_x4(bb4, bb_base + (unsigned)(nf2 * 16) * (PAD2 * 2) + (unsigned)(ks * 32));
                #pragma unroll
                for (int mf = 0; mf < 2; mf++) {
                    mma_f16(acc[mf][nf2 * 2],     a[mf], bb4);
                    mma_f16(acc[mf][nf2 * 2 + 1], a[mf], bb4 + 2);
                }
            }
        }

        if (have_next) {
            __half2 w0 = __float2half2_rn(wf.x), w1 = __float2half2_rn(wf.y);
            __half2 w2 = __float2half2_rn(wf.z), w3 = __float2half2_rn(wf.w);
            *(uint4*)&As[nxt * AS_ELEMS + as_off[1]] = blend8(r0, r1, r2, r3, w0, w1, w2, w3);
            cp_async_wait0();
        }
        __syncthreads();
    }

    // ---- epilogue: BN(+bias) + ReLU, write NCHW ----
    int g = lane >> 2;
    int cq = (lane & 3) * 2;
    #pragma unroll
    for (int mf = 0; mf < 2; mf++) {
        int row0 = m_base + wm * 32 + mf * 16 + g;
        #pragma unroll
        for (int half = 0; half < 2; half++) {
            int m = row0 + half * 8;
            int b = m >> 12, h = (m >> 6) & 63, w = m & 63;
            float* orow = out + ((size_t)b * CO * HN + h) * WN + w;
            #pragma unroll
            for (int nf = 0; nf < 8; nf++) {
                int nl0 = wn * 64 + nf * 8 + cq;
                #pragma unroll
                for (int j = 0; j < 2; j++) {
                    int nl = nl0 + j;
                    float v = acc[mf][nf][half * 2 + j] * s_scale[nl] + s_shift[nl];
                    orow[(size_t)nl * HN * WN] = fmaxf(v, 0.f);
                }
            }
        }
    }
}

// ---------------- launch ----------------
#define KMAIN_SMEM (2*AS_ELEMS*2 + 2*BS_ELEMS*2 + 2*128*16 + 2*128*16 + 2*256*4)

extern "C" void kernel_launch(void* const* d_in, const int* in_sizes, int n_in,
                              void* d_out, int out_size) {
    const float* x      = (const float*)d_in[0];
    const float* w_off  = (const float*)d_in[1];
    const float* b_off  = (const float*)d_in[2];
    const float* weight = (const float*)d_in[3];
    const float* bias   = (const float*)d_in[4];
    const float* gamma  = (const float*)d_in[5];
    const float* beta   = (const float*)d_in[6];
    const float* rmean  = (const float*)d_in[7];
    const float* rvar   = (const float*)d_in[8];
    float* out = (float*)d_out;

    static bool attr_done = false;
    if (!attr_done) {
        cudaFuncSetAttribute(k_main, cudaFuncAttributeMaxDynamicSharedMemorySize, KMAIN_SMEM);
        cudaFuncSetAttribute(k_offconv, cudaFuncAttributeMaxDynamicSharedMemorySize, KOFF_SMEM);
        attr_done = true;
    }

    k_prep<<<PREP_TRANSPOSE_BLKS + CO + 32, 256>>>(x, w_off, weight);
    k_offconv<<<BN_ * HN, 256, KOFF_SMEM>>>(b_off);
    k_main<<<BN_ * HN * WN / 128, 512, KMAIN_SMEM>>>(bias, gamma, beta, rmean, rvar, out);
}